// round 16
// baseline (speedup 1.0000x reference)
#include <cuda_runtime.h>
#include <cuda_fp16.h>
#include <math.h>
#include <stdint.h>

#define BB    16
#define HH    128
#define WW    128
#define HWSZ  (HH*WW)
#define NPX   (BB*HWSZ)         // 262144
#define NTILE 2048              // BB*HH
#define CSP   63

typedef unsigned short ushortt;

// ------------------------------ scratch ------------------------------------
__device__ __align__(16) ushortt g_xh[(size_t)NPX*32];
__device__ __align__(16) ushortt g_s1[(size_t)NPX*64];   // fp16 NHWC
__device__ __align__(16) ushortt g_s2[(size_t)NPX*64];   // fp16 NHWC
__device__ __align__(16) ushortt g_spb[(size_t)NPX*64];  // fp16 NHWC
__device__ __align__(16) ushortt g_B1[10*64*40];     // fp16, padded 80B rows
__device__ __align__(16) ushortt g_B2[9*64*64];      // fp16, SW128-xor 128B rows
__device__ float g_part[3*(size_t)NTILE*128];        // [tile][64][2]
__device__ float g_stats[3*64*2];

// ------------------------------ PTX helpers --------------------------------
__device__ __forceinline__ uint32_t smem_u32(const void* p) {
    uint32_t a;
    asm("{ .reg .u64 t; cvta.to.shared.u64 t, %1; cvt.u32.u64 %0, t; }" : "=r"(a) : "l"(p));
    return a;
}
#define LDSM4(a, addr) \
    asm volatile("ldmatrix.sync.aligned.m8n8.x4.shared.b16 {%0,%1,%2,%3}, [%4];" \
        : "=r"((a)[0]), "=r"((a)[1]), "=r"((a)[2]), "=r"((a)[3]) : "r"(addr))
#define LDSM2(b0, b1, addr) \
    asm volatile("ldmatrix.sync.aligned.m8n8.x2.shared.b16 {%0,%1}, [%2];" \
        : "=r"(b0), "=r"(b1) : "r"(addr))
#define MMA(d, a, b0, b1) \
    asm volatile("mma.sync.aligned.m16n8k16.row.col.f32.f16.f16.f32 " \
        "{%0,%1,%2,%3},{%4,%5,%6,%7},{%8,%9},{%0,%1,%2,%3};" \
        : "+f"((d)[0]), "+f"((d)[1]), "+f"((d)[2]), "+f"((d)[3]) \
        : "r"((a)[0]), "r"((a)[1]), "r"((a)[2]), "r"((a)[3]), "r"(b0), "r"(b1))

__device__ __forceinline__ void cpasync16(uint32_t dst, const void* src, bool ok) {
    int sz = ok ? 16 : 0;
    asm volatile("cp.async.cg.shared.global [%0], [%1], 16, %2;"
                 :: "r"(dst), "l"(src), "r"(sz) : "memory");
}
#define CP_COMMIT() asm volatile("cp.async.commit_group;" ::: "memory")
#define CP_WAIT0()  asm volatile("cp.async.wait_group 0;" ::: "memory")
#define CP_WAIT1()  asm volatile("cp.async.wait_group 1;" ::: "memory")
#define CP_WAIT2()  asm volatile("cp.async.wait_group 2;" ::: "memory")

// ===========================================================================
// conv1 + 1x1 shortcut: row-streaming, 4-slot ring, single-row tiles.
// (Exact R13 structure — 95KB smem, 2 CTAs/SM.)
// ===========================================================================
__global__ void __launch_bounds__(256, 2)
conv1_k(const ushortt* __restrict__ Ah_g, const ushortt* __restrict__ Bimg,
        const float* __restrict__ bias0, const float* __restrict__ bias1,
        ushortt* __restrict__ out0, ushortt* __restrict__ out1,
        float* __restrict__ part0, float* __restrict__ part1)
{
    constexpr int CCH    = 32;
    constexpr int STRIDE = 80;
    constexpr int SEGJ   = 4;
    constexpr int ROWPX  = 130;
    constexpr int ROWSZ  = ROWPX * STRIDE;   // 10400
    constexpr int ABUF   = 2560;
    constexpr int BOFF   = ABUF + 4 * ROWSZ; // 44160
    constexpr int BTAPSZ = 64 * 80;
    constexpr int BSZ    = 10 * BTAPSZ;      // 51200
    constexpr int NS     = 18;

    extern __shared__ __align__(16) char smem[];
    const uint32_t sb = smem_u32(smem);
    const int t = threadIdx.x, wid = t >> 5, lane = t & 31;

    float* biasm = (float*)smem;                 // [128]
    float* redsm = (float*)(smem + 512);         // [8][32][2]

    if (t < 64)  biasm[t] = (t < CSP) ? bias0[t] : 0.f;
    else if (t < 128) biasm[t] = ((t - 64) < CSP) ? bias1[t - 64] : 0.f;

    {
        const uint4* src = (const uint4*)Bimg;
        uint4* dst = (uint4*)(smem + BOFF);
        for (int i = t; i < BSZ/16; i += 256) dst[i] = src[i];
    }

    const int mw = wid & 3, nw = wid >> 2;
    const int rid = lane & 7, grp = lane >> 3;
    const int qrow = lane >> 2, qc = lane & 3;
    const int arow = mw*32 + (grp & 1)*8 + rid;
    const int au0  = grp >> 1;
    const int bu0  = grp & 1;

    const int img = blockIdx.x / NS;
    const int sub = blockIdx.x % NS;
    constexpr int BASE = 128 / NS, REM = 128 % NS;
    const int r0y  = sub*BASE + (sub < REM ? sub : REM);
    const int len  = BASE + (sub < REM ? 1 : 0);
    const int yend = r0y + len;

    auto stage_row = [&](int yy) {
        const int slot = (yy + 1) & 3;
        const bool rowok = (yy >= 0) && (yy < HH);
        const int yyc = rowok ? yy : 0;
        const size_t rowbase = (size_t)((img << 7) + yyc) * 128 * CCH;
        for (int s = t; s < ROWPX*SEGJ; s += 256) {
            const int pxi = s / SEGJ, j = s - pxi*SEGJ;
            const int ix = pxi - 1;
            const bool ok = rowok && (ix >= 0) && (ix < WW);
            const int ixc = ok ? ix : 0;
            const void* g = (const void*)(Ah_g + rowbase + (size_t)ixc*CCH + j*8);
            const uint32_t d = sb + ABUF + (uint32_t)(slot*ROWSZ + pxi*STRIDE + j*16);
            cpasync16(d, g, ok);
        }
        CP_COMMIT();
    };

    auto baddr = [&](int btap, int nf, int kc) -> uint32_t {
        const int oc = nw*32 + nf*8 + rid;
        const int u  = kc*2 + bu0;
        return sb + BOFF + (uint32_t)(btap*BTAPSZ + oc*80 + u*16);
    };

    auto compute_tap = [&](uint32_t Abase, int btap, float (*ac)[4][4]) {
#pragma unroll
        for (int kc = 0; kc < 2; kc++) {
            uint32_t a0[4], a1[4];
            const uint32_t aoff = (uint32_t)((au0 + kc*2)*16);
            LDSM4(a0, Abase + (uint32_t)(arow       *STRIDE) + aoff);
            LDSM4(a1, Abase + (uint32_t)((arow + 16)*STRIDE) + aoff);
#pragma unroll
            for (int nf = 0; nf < 4; nf++) {
                uint32_t b0, b1;
                LDSM2(b0, b1, baddr(btap, nf, kc));
                MMA(ac[0][nf], a0, b0, b1);
                MMA(ac[1][nf], a1, b0, b1);
            }
        }
    };

    auto epilogue = [&](float (*ac)[4][4], const float* bsm,
                        ushortt* outT, float* pp, int y) {
        __syncthreads();                         // redsm reuse guard
        const size_t tile = (size_t)(img*128 + y);
        ushortt* ob = outT + tile*8192;
#pragma unroll
        for (int nf = 0; nf < 4; nf++) {
            const int c0 = nw*32 + nf*8 + qc*2;
            const float bb0 = bsm[c0], bb1 = bsm[c0 + 1];
            float s0 = 0.f, s1v = 0.f, q0 = 0.f, q1 = 0.f;
#pragma unroll
            for (int mi = 0; mi < 2; mi++)
#pragma unroll
                for (int rr = 0; rr < 2; rr++) {
                    const int row = mw*32 + mi*16 + rr*8 + qrow;
                    const float v0 = ac[mi][nf][rr*2 + 0] + bb0;
                    const float v1 = ac[mi][nf][rr*2 + 1] + bb1;
                    *(__half2*)(ob + (size_t)row*64 + c0) = __floats2half2_rn(v0, v1);
                    s0 += v0; s1v += v1;
                    q0 = fmaf(v0, v0, q0); q1 = fmaf(v1, v1, q1);
                }
#pragma unroll
            for (int off = 4; off < 32; off <<= 1) {
                s0  += __shfl_xor_sync(0xffffffffu, s0,  off);
                s1v += __shfl_xor_sync(0xffffffffu, s1v, off);
                q0  += __shfl_xor_sync(0xffffffffu, q0,  off);
                q1  += __shfl_xor_sync(0xffffffffu, q1,  off);
            }
            if (qrow == 0) {
                const int lc = nf*8 + qc*2;
                redsm[(wid*32 + lc)*2 + 0] = s0;
                redsm[(wid*32 + lc)*2 + 1] = q0;
                redsm[(wid*32 + lc + 1)*2 + 0] = s1v;
                redsm[(wid*32 + lc + 1)*2 + 1] = q1;
            }
        }
        __syncthreads();
        if (t < 64) {
            float s = 0.f, q = 0.f;
#pragma unroll
            for (int mwi = 0; mwi < 4; mwi++) {
                const int idx = (((t >> 5)*4 + mwi)*32 + (t & 31))*2;
                s += redsm[idx]; q += redsm[idx + 1];
            }
            pp[tile*128 + t*2 + 0] = s;
            pp[tile*128 + t*2 + 1] = q;
        }
    };

    stage_row(r0y - 1);
    stage_row(r0y);
    stage_row(r0y + 1);

    for (int oy = r0y; oy < yend; oy++) {
        __syncthreads();
        const bool st = (oy + 2 <= yend);
        if (st) { stage_row(oy + 2); CP_WAIT1(); }
        else    { CP_WAIT0(); }
        __syncthreads();

        float acc[2][4][4];
#pragma unroll
        for (int mi = 0; mi < 2; mi++)
#pragma unroll
            for (int nf = 0; nf < 4; nf++)
#pragma unroll
                for (int k = 0; k < 4; k++) acc[mi][nf][k] = 0.f;

#pragma unroll
        for (int ky = 0; ky < 3; ky++) {
            const uint32_t slotbase = sb + ABUF + (uint32_t)(((oy + ky) & 3) * ROWSZ);
#pragma unroll
            for (int kx = 0; kx < 3; kx++)
                compute_tap(slotbase + (uint32_t)(kx*STRIDE), ky*3 + kx, acc);
        }
        epilogue(acc, biasm, out0, part0, oy);

        {
            float accp[2][4][4];
#pragma unroll
            for (int mi = 0; mi < 2; mi++)
#pragma unroll
                for (int nf = 0; nf < 4; nf++)
#pragma unroll
                    for (int k = 0; k < 4; k++) accp[mi][nf][k] = 0.f;
            const uint32_t cbase = sb + ABUF + (uint32_t)(((oy + 1) & 3) * ROWSZ);
            compute_tap(cbase + (uint32_t)STRIDE, 9, accp);
            epilogue(accp, biasm + 64, out1, part1, oy);
        }
    }
}

// ===========================================================================
// conv2: 512 threads (16 warps), 2-row M=256 tiles, 8 M-splits x 2 N-splits.
// 6-slot ring, fused bnrp in staging. fp16 output.
// ===========================================================================
__global__ void __launch_bounds__(512, 1)
conv2_k(const ushortt* __restrict__ S1g, const ushortt* __restrict__ Bimg,
        const float* __restrict__ bias0, const float* __restrict__ st1,
        ushortt* __restrict__ out0, float* __restrict__ part0)
{
    constexpr int CCH    = 64;
    constexpr int STRIDE = 144;
    constexpr int SEGJ   = 8;
    constexpr int ROWPX  = 130;
    constexpr int ROWSZ  = ROWPX * STRIDE;   // 18720
    constexpr int ABUF   = 5120;             // biasm/abn/bbn + redsm[16][32][2]
    constexpr int BOFF   = ABUF + 6 * ROWSZ; // 117440
    constexpr int BTAPSZ = 64 * 128;
    constexpr int BSZ    = 9 * BTAPSZ;       // 73728

    extern __shared__ __align__(16) char smem[];
    const uint32_t sb = smem_u32(smem);
    const int t = threadIdx.x, wid = t >> 5, lane = t & 31;

    float* biasm = (float*)smem;                 // [64]
    float* abn   = (float*)(smem + 256);         // [64]
    float* bbn   = (float*)(smem + 512);         // [64]
    float* redsm = (float*)(smem + 1024);        // [16][32][2] = 4096B

    if (t < 64) {
        biasm[t] = (t < CSP) ? bias0[t] : 0.f;
        abn[t]   = (t < CSP) ? st1[2*t]   : 0.f;
        bbn[t]   = (t < CSP) ? st1[2*t+1] : 0.f;
    }

    {
        const uint4* src = (const uint4*)Bimg;
        uint4* dst = (uint4*)(smem + BOFF);
        for (int i = t; i < BSZ/16; i += 512) dst[i] = src[i];
    }
    __syncthreads();   // abn/bbn visible before convert

    // warp layout: 8 M-splits (32 px each over 2 rows) x 2 N-splits
    const int nw   = wid & 1;
    const int mloc = wid >> 1;                // 0..7
    const int rowr = mloc >> 2;               // which of the 2 output rows
    const int px0  = (mloc & 3) * 32;         // px base within row
    const int rid = lane & 7, grp = lane >> 3;
    const int qrow = lane >> 2, qc = lane & 3;
    const int arowb = px0 + (grp & 1)*8 + rid;
    const int au0  = grp >> 1;
    const int bu0  = grp & 1;

    const int img = blockIdx.x / 9;
    const int sub = blockIdx.x % 9;
    const int r0y  = (sub == 0) ? 0 : 16 + (sub - 1)*14;
    const int len  = (sub == 0) ? 16 : 14;
    const int yend = r0y + len;

    auto slotof = [&](int row) -> int { return (row + 1) % 6; };

    auto stage_row = [&](int yy) {
        const int slot = slotof(yy);
        const bool rowok = (yy >= 0) && (yy < HH);
        const int yyc = rowok ? yy : 0;
        const size_t rowbase = (size_t)((img << 7) + yyc) * 128 * CCH;
        for (int s = t; s < ROWPX*SEGJ; s += 512) {
            const int pxi = s / SEGJ, j = s - pxi*SEGJ;
            const int ix = pxi - 1;
            const bool ok = rowok && (ix >= 0) && (ix < WW);
            const int ixc = ok ? ix : 0;
            const void* g = (const void*)(S1g + rowbase + (size_t)ixc*CCH + j*8);
            const uint32_t d = sb + ABUF + (uint32_t)(slot*ROWSZ + pxi*STRIDE + j*16);
            cpasync16(d, g, ok);
        }
        CP_COMMIT();
    };

    auto convert_row = [&](int yy) {
        const bool rowok = (yy >= 0) && (yy < HH);
        char* slotp = smem + ABUF + slotof(yy)*ROWSZ;
        for (int p = t; p < ROWPX; p += 512) {
            char* pxp = slotp + p*STRIDE;
            if (!rowok || p == 0 || p == ROWPX-1) {
                const uint4 z = make_uint4(0u,0u,0u,0u);
#pragma unroll
                for (int j = 0; j < 8; j++) *(uint4*)(pxp + j*16) = z;
            } else {
                uint4 raw[8];
#pragma unroll
                for (int j = 0; j < 8; j++) raw[j] = *(const uint4*)(pxp + j*16);
                const __half2* rh = (const __half2*)raw;
                ushortt h[64];
                float q = 0.f;
#pragma unroll
                for (int c2 = 0; c2 < 32; c2++) {
                    float2 f = __half22float2(rh[c2]);
                    const int c0 = 2*c2, c1 = c0 + 1;
                    float r0 = fmaxf(fmaf(abn[c0], f.x, bbn[c0]), 0.f);
                    q = fmaf(r0, r0, q);
                    __half h0 = __float2half_rn(r0);
                    h[c0+1] = *(ushortt*)&h0;
                    if (c1 < CSP) {
                        float r1 = fmaxf(fmaf(abn[c1], f.y, bbn[c1]), 0.f);
                        q = fmaf(r1, r1, q);
                        __half h1 = __float2half_rn(r1);
                        h[c1+1] = *(ushortt*)&h1;
                    }
                }
                float tv = sqrtf(1.f + q);
                __half ht = __float2half_rn(tv);
                h[0] = *(ushortt*)&ht;
#pragma unroll
                for (int j = 0; j < 8; j++) *(uint4*)(pxp + j*16) = ((uint4*)h)[j];
            }
        }
    };

    auto baddr = [&](int btap, int nf, int kc) -> uint32_t {
        const int oc = nw*32 + nf*8 + rid;
        const int u  = kc*2 + bu0;
        return sb + BOFF + (uint32_t)(btap*BTAPSZ + oc*128 + ((u ^ (oc & 7)) * 16));
    };

    stage_row(r0y - 1);
    stage_row(r0y);
    stage_row(r0y + 1);
    stage_row(r0y + 2);
    CP_WAIT2();
    __syncthreads();
    convert_row(r0y - 1);
    convert_row(r0y);

    for (int oy = r0y; oy < yend; oy += 2) {
        __syncthreads();                        // ring-slot + redsm reuse guard
        const bool st = (oy + 2 < yend);
        if (st) { stage_row(oy + 3); stage_row(oy + 4); CP_WAIT2(); }
        else    { CP_WAIT0(); }
        __syncthreads();
        convert_row(oy + 1);
        convert_row(oy + 2);
        __syncthreads();

        float acc[2][4][4];
#pragma unroll
        for (int mi = 0; mi < 2; mi++)
#pragma unroll
            for (int nf = 0; nf < 4; nf++)
#pragma unroll
                for (int k = 0; k < 4; k++) acc[mi][nf][k] = 0.f;

#pragma unroll
        for (int ky = 0; ky < 3; ky++) {
            const int inrow = oy + rowr + ky - 1;
            const uint32_t slotb = sb + ABUF + (uint32_t)(slotof(inrow) * ROWSZ);
#pragma unroll
            for (int kx = 0; kx < 3; kx++) {
                const int tap = ky*3 + kx;
                const uint32_t Abase = slotb + (uint32_t)(kx*STRIDE);
#pragma unroll
                for (int kc = 0; kc < 4; kc++) {
                    uint32_t a0[4], a1[4];
                    const uint32_t aoff = (uint32_t)((au0 + kc*2)*16);
                    LDSM4(a0, Abase + (uint32_t)((arowb     )*STRIDE) + aoff);
                    LDSM4(a1, Abase + (uint32_t)((arowb + 16)*STRIDE) + aoff);
#pragma unroll
                    for (int nf = 0; nf < 4; nf++) {
                        uint32_t b0, b1;
                        LDSM2(b0, b1, baddr(tap, nf, kc));
                        MMA(acc[0][nf], a0, b0, b1);
                        MMA(acc[1][nf], a1, b0, b1);
                    }
                }
            }
        }

        // epilogue: each warp writes its 32px x 32oc; partials [tile][64][2]
        {
            const size_t tile = (size_t)(img*128 + oy + rowr);
            ushortt* ob = out0 + tile*8192;
#pragma unroll
            for (int nf = 0; nf < 4; nf++) {
                const int c0 = nw*32 + nf*8 + qc*2;
                const float bb0 = biasm[c0], bb1 = biasm[c0 + 1];
                float s0 = 0.f, s1v = 0.f, q0 = 0.f, q1 = 0.f;
#pragma unroll
                for (int mi = 0; mi < 2; mi++)
#pragma unroll
                    for (int rr = 0; rr < 2; rr++) {
                        const int px = px0 + mi*16 + rr*8 + qrow;
                        const float v0 = acc[mi][nf][rr*2 + 0] + bb0;
                        const float v1 = acc[mi][nf][rr*2 + 1] + bb1;
                        *(__half2*)(ob + (size_t)px*64 + c0) = __floats2half2_rn(v0, v1);
                        s0 += v0; s1v += v1;
                        q0 = fmaf(v0, v0, q0); q1 = fmaf(v1, v1, q1);
                    }
#pragma unroll
                for (int off = 4; off < 32; off <<= 1) {
                    s0  += __shfl_xor_sync(0xffffffffu, s0,  off);
                    s1v += __shfl_xor_sync(0xffffffffu, s1v, off);
                    q0  += __shfl_xor_sync(0xffffffffu, q0,  off);
                    q1  += __shfl_xor_sync(0xffffffffu, q1,  off);
                }
                if (qrow == 0) {
                    const int lc = nf*8 + qc*2;
                    redsm[(wid*32 + lc)*2 + 0] = s0;
                    redsm[(wid*32 + lc)*2 + 1] = q0;
                    redsm[(wid*32 + lc + 1)*2 + 0] = s1v;
                    redsm[(wid*32 + lc + 1)*2 + 1] = q1;
                }
            }
            __syncthreads();
            if (t < 128) {
                const int r = t >> 6, c = t & 63;
                const int nw2 = c >> 5;
                float s = 0.f, q = 0.f;
#pragma unroll
                for (int m = 0; m < 4; m++) {
                    const int w2 = ((r*4 + m)*2) + nw2;
                    const int i0 = (w2*32 + (c & 31))*2;
                    s += redsm[i0]; q += redsm[i0 + 1];
                }
                const size_t tr = (size_t)(img*128 + oy + r);
                part0[tr*128 + c*2 + 0] = s;
                part0[tr*128 + c*2 + 1] = q;
            }
        }
    }
}

// ---------------------------------------------------------------------------
// x NCHW fp32 -> NHWC fp16
__global__ __launch_bounds__(256)
void splitx_k(const float* __restrict__ x, ushortt* __restrict__ xh)
{
    int px = blockIdx.x*256 + threadIdx.x;
    int b = px >> 14, pix = px & (HWSZ - 1);
    const float* xb = x + (size_t)b*32*HWSZ + pix;
    ushortt h[32];
#pragma unroll
    for (int c = 0; c < 32; c++) {
        __half hh = __float2half_rn(xb[(size_t)c*HWSZ]);
        h[c] = *(ushortt*)&hh;
    }
    uint4* dh = (uint4*)(xh + (size_t)px*32);
#pragma unroll
    for (int i = 0; i < 4; i++) dh[i] = ((uint4*)h)[i];
}

// w1 + wp -> fp16 B1 image (padded 80B rows)
__global__ __launch_bounds__(256)
void splitw1_k(const float* __restrict__ w1, const float* __restrict__ wp,
               ushortt* __restrict__ B1)
{
    const int i = blockIdx.x*256 + threadIdx.x;
    if (i >= 25600) return;                           // B1: [10][64][40]
    int tap = i / 2560, r2 = i % 2560, oc = r2 / 40, s = r2 % 40;
    float val = 0.f;
    if (s < 32 && oc < CSP) {
        if (tap < 9) { int ky = tap/3, kx = tap%3; val = w1[((oc*32 + s)*3 + ky)*3 + kx]; }
        else         { val = wp[oc*32 + s]; }
    }
    __half hv = __float2half_rn(val);
    B1[i] = *(ushortt*)&hv;
}

// w2 -> fp16 B2 image (SW128-xor 128B rows)
__global__ __launch_bounds__(256)
void splitw2_k(const float* __restrict__ w2, ushortt* __restrict__ B2)
{
    const int k = blockIdx.x*256 + threadIdx.x;
    if (k >= 36864) return;                           // B2: [9][64][64]
    int tap = k / 4096, r2 = k % 4096, oc = r2 / 64, ps = r2 % 64;
    int u_log = (ps >> 3) ^ (oc & 7);
    int c = u_log*8 + (ps & 7);
    float val = 0.f;
    if (oc < CSP) { int ky = tap/3, kx = tap%3; val = w2[((oc*64 + c)*3 + ky)*3 + kx]; }
    __half hv = __float2half_rn(val);
    B2[k] = *(ushortt*)&hv;
}

// BN finalize, [tile][64][2] partials, 1024 threads; two stats per grid
__global__ __launch_bounds__(1024)
void stats2_k(const float* __restrict__ partA, const float* __restrict__ gA,
              const float* __restrict__ btA, float* __restrict__ stA,
              const float* __restrict__ partB, const float* __restrict__ gB,
              const float* __restrict__ btB, float* __restrict__ stB)
{
    __shared__ double ss[1024], qq[1024];
    const bool second = (blockIdx.x >= 63);
    const int c = second ? (blockIdx.x - 63) : blockIdx.x;
    const float* part = second ? partB : partA;
    const float* gamma = second ? gB : gA;
    const float* beta  = second ? btB : btA;
    float* stats = second ? stB : stA;
    const int t = threadIdx.x;
    double s = 0.0, q = 0.0;
#pragma unroll
    for (int i = 0; i < NTILE/1024; i++) {
        const float* p = part + (size_t)(i*1024 + t)*128 + c*2;
        s += (double)p[0]; q += (double)p[1];
    }
    ss[t] = s; qq[t] = q;
#pragma unroll
    for (int off = 512; off > 0; off >>= 1) {
        __syncthreads();
        if (t < off) { ss[t] += ss[t+off]; qq[t] += qq[t+off]; }
    }
    if (t == 0) {
        const double n = (double)NPX;
        double mu  = ss[0] / n;
        double var = qq[0] / n - mu*mu;
        float rstd = (float)(1.0 / sqrt(var + 1e-5));
        float a  = gamma[c] * rstd;
        float bc = beta[c] - a * (float)mu;
        stats[c*2] = a; stats[c*2+1] = bc;
    }
}

// merge + relu + project -> out NCHW fp32; s2/sp fp16
__global__ __launch_bounds__(256)
void final_k(const ushortt* __restrict__ s2, const ushortt* __restrict__ sp,
             const float* __restrict__ st2, const float* __restrict__ stp,
             float* __restrict__ out)
{
    __shared__ float a2[64], b2[64], ap[64], bp[64];
    int t = threadIdx.x;
    if (t < 64) {
        a2[t] = (t < CSP) ? st2[2*t]   : 0.f;
        b2[t] = (t < CSP) ? st2[2*t+1] : 0.f;
        ap[t] = (t < CSP) ? stp[2*t]   : 0.f;
        bp[t] = (t < CSP) ? stp[2*t+1] : 0.f;
    }
    __syncthreads();
    size_t px = (size_t)blockIdx.x*256 + t;
    int b = (int)(px >> 14), pix = (int)(px & (HWSZ - 1));
    const __half2* p2 = (const __half2*)(s2 + px*64);
    const __half2* pq = (const __half2*)(sp + px*64);
    float r[CSP]; float q = 0.f;
#pragma unroll
    for (int c2 = 0; c2 < 32; c2++) {
        float2 f2 = __half22float2(p2[c2]);
        float2 fq = __half22float2(pq[c2]);
        const int c0 = 2*c2, c1 = 2*c2 + 1;
        float h0 = fmaf(a2[c0], f2.x, b2[c0]) + fmaf(ap[c0], fq.x, bp[c0]);
        r[c0] = fmaxf(h0, 0.f);
        q = fmaf(r[c0], r[c0], q);
        if (c1 < CSP) {
            float h1 = fmaf(a2[c1], f2.y, b2[c1]) + fmaf(ap[c1], fq.y, bp[c1]);
            r[c1] = fmaxf(h1, 0.f);
            q = fmaf(r[c1], r[c1], q);
        }
    }
    float* ob = out + (size_t)b*64*HWSZ + pix;
    ob[0] = sqrtf(1.f + q);
#pragma unroll
    for (int c = 0; c < CSP; c++) ob[(size_t)(c+1)*HWSZ] = r[c];
}

// ---------------------------------------------------------------------------
extern "C" void kernel_launch(void* const* d_in, const int* in_sizes, int n_in,
                              void* d_out, int out_size)
{
    const float* x   = (const float*)d_in[0];
    const float* w1  = (const float*)d_in[1];
    const float* b1  = (const float*)d_in[2];
    const float* g1  = (const float*)d_in[3];
    const float* bt1 = (const float*)d_in[4];
    const float* w2  = (const float*)d_in[5];
    const float* b2  = (const float*)d_in[6];
    const float* g2  = (const float*)d_in[7];
    const float* bt2 = (const float*)d_in[8];
    const float* wp  = (const float*)d_in[9];
    const float* bp  = (const float*)d_in[10];
    const float* gp  = (const float*)d_in[11];
    const float* btp = (const float*)d_in[12];
    float* out = (float*)d_out;

    void *pxh,*ps1,*ps2,*psp,*pB1,*pB2,*ppart,*pstats;
    cudaGetSymbolAddress(&pxh, g_xh);
    cudaGetSymbolAddress(&ps1, g_s1);
    cudaGetSymbolAddress(&ps2, g_s2);
    cudaGetSymbolAddress(&psp, g_spb);  cudaGetSymbolAddress(&pB1, g_B1);
    cudaGetSymbolAddress(&pB2, g_B2);   cudaGetSymbolAddress(&ppart, g_part);
    cudaGetSymbolAddress(&pstats, g_stats);
    ushortt* xh = (ushortt*)pxh;
    ushortt* s1 = (ushortt*)ps1;
    ushortt* s2 = (ushortt*)ps2;
    ushortt* sp = (ushortt*)psp;
    ushortt* B1 = (ushortt*)pB1;
    ushortt* B2 = (ushortt*)pB2;
    float* part  = (float*)ppart;
    float* stats = (float*)pstats;

    const int SM1 = 2560 + 4*(130*80)  + 10*64*80;   // 95,360  (2 CTAs/SM)
    const int SM2 = 5120 + 6*(130*144) + 9*64*128;   // 191,168 (1 CTA/SM)
    cudaFuncSetAttribute((const void*)conv1_k,
                         cudaFuncAttributeMaxDynamicSharedMemorySize, SM1);
    cudaFuncSetAttribute((const void*)conv2_k,
                         cudaFuncAttributeMaxDynamicSharedMemorySize, SM2);

    const size_t PS = (size_t)NTILE*128;

    splitw1_k<<<100, 256>>>(w1, wp, B1);
    splitw2_k<<<144, 256>>>(w2, B2);
    splitx_k<<<NPX/256, 256>>>(x, xh);
    conv1_k<<<16*18, 256, SM1>>>(xh, B1, b1, bp, s1, sp,
                                 part + 0*PS, part + 2*PS);
    stats2_k<<<63, 1024>>>(part + 0*PS, g1, bt1, stats + 0*64*2,
                           nullptr, nullptr, nullptr, nullptr);
    conv2_k<<<16*9, 512, SM2>>>(s1, B2, b2, stats + 0*64*2, s2, part + 1*PS);
    stats2_k<<<126, 1024>>>(part + 1*PS, g2, bt2, stats + 1*64*2,
                            part + 2*PS, gp, btp, stats + 2*64*2);
    final_k<<<NPX/256, 256>>>(s2, sp, stats + 1*64*2, stats + 2*64*2, out);
}

// round 17
// speedup vs baseline: 1.0516x; 1.0516x over previous
#include <cuda_runtime.h>
#include <cuda_fp16.h>
#include <math.h>
#include <stdint.h>

#define BB    16
#define HH    128
#define WW    128
#define HWSZ  (HH*WW)
#define NPX   (BB*HWSZ)         // 262144
#define CSP   63

typedef unsigned short ushortt;

// ------------------------------ scratch ------------------------------------
__device__ __align__(16) ushortt g_xh[(size_t)NPX*32];
__device__ __align__(16) ushortt g_s1[(size_t)NPX*64];   // fp16 NHWC
__device__ __align__(16) ushortt g_s2[(size_t)NPX*64];   // fp16 NHWC
__device__ __align__(16) ushortt g_spb[(size_t)NPX*64];  // fp16 NHWC
__device__ __align__(16) ushortt g_B1[10*64*40];     // fp16, padded 80B rows
__device__ __align__(16) ushortt g_B2[9*64*64];      // fp16, SW128-xor 128B rows
#define PSZ (288*128)
__device__ float g_part[3*(size_t)PSZ];              // per-CTA partials [cta][64][2]
__device__ float g_stats[3*64*2];

// ------------------------------ PTX helpers --------------------------------
__device__ __forceinline__ uint32_t smem_u32(const void* p) {
    uint32_t a;
    asm("{ .reg .u64 t; cvta.to.shared.u64 t, %1; cvt.u32.u64 %0, t; }" : "=r"(a) : "l"(p));
    return a;
}
#define LDSM4(a, addr) \
    asm volatile("ldmatrix.sync.aligned.m8n8.x4.shared.b16 {%0,%1,%2,%3}, [%4];" \
        : "=r"((a)[0]), "=r"((a)[1]), "=r"((a)[2]), "=r"((a)[3]) : "r"(addr))
#define LDSM2(b0, b1, addr) \
    asm volatile("ldmatrix.sync.aligned.m8n8.x2.shared.b16 {%0,%1}, [%2];" \
        : "=r"(b0), "=r"(b1) : "r"(addr))
#define MMA(d, a, b0, b1) \
    asm volatile("mma.sync.aligned.m16n8k16.row.col.f32.f16.f16.f32 " \
        "{%0,%1,%2,%3},{%4,%5,%6,%7},{%8,%9},{%0,%1,%2,%3};" \
        : "+f"((d)[0]), "+f"((d)[1]), "+f"((d)[2]), "+f"((d)[3]) \
        : "r"((a)[0]), "r"((a)[1]), "r"((a)[2]), "r"((a)[3]), "r"(b0), "r"(b1))

__device__ __forceinline__ void cpasync16(uint32_t dst, const void* src, bool ok) {
    int sz = ok ? 16 : 0;
    asm volatile("cp.async.cg.shared.global [%0], [%1], 16, %2;"
                 :: "r"(dst), "l"(src), "r"(sz) : "memory");
}
#define CP_COMMIT() asm volatile("cp.async.commit_group;" ::: "memory")
#define CP_WAIT0()  asm volatile("cp.async.wait_group 0;" ::: "memory")
#define CP_WAIT1()  asm volatile("cp.async.wait_group 1;" ::: "memory")
#define CP_WAIT2()  asm volatile("cp.async.wait_group 2;" ::: "memory")

// ===========================================================================
// conv1 + 1x1 shortcut: row-streaming, 4-slot ring, single-row tiles.
// Per-CTA BN partial accumulation in smem; one gmem write at exit.
// ===========================================================================
__global__ void __launch_bounds__(256, 2)
conv1_k(const ushortt* __restrict__ Ah_g, const ushortt* __restrict__ Bimg,
        const float* __restrict__ bias0, const float* __restrict__ bias1,
        ushortt* __restrict__ out0, ushortt* __restrict__ out1,
        float* __restrict__ part0, float* __restrict__ part1)
{
    constexpr int CCH    = 32;
    constexpr int STRIDE = 80;
    constexpr int SEGJ   = 4;
    constexpr int ROWPX  = 130;
    constexpr int ROWSZ  = ROWPX * STRIDE;   // 10400
    constexpr int ABUF   = 3584;             // biasm(512) + redsm(2048) + accs(1024)
    constexpr int BOFF   = ABUF + 4 * ROWSZ; // 45184
    constexpr int BTAPSZ = 64 * 80;
    constexpr int BSZ    = 10 * BTAPSZ;      // 51200
    constexpr int NS     = 18;

    extern __shared__ __align__(16) char smem[];
    const uint32_t sb = smem_u32(smem);
    const int t = threadIdx.x, wid = t >> 5, lane = t & 31;

    float* biasm = (float*)smem;                 // [128]
    float* redsm = (float*)(smem + 512);         // [8][32][2]
    float* accs  = (float*)(smem + 2560);        // [2][128]

    if (t < 64)  biasm[t] = (t < CSP) ? bias0[t] : 0.f;
    else if (t < 128) biasm[t] = ((t - 64) < CSP) ? bias1[t - 64] : 0.f;
    if (t < 256) accs[t] = 0.f;

    {
        const uint4* src = (const uint4*)Bimg;
        uint4* dst = (uint4*)(smem + BOFF);
        for (int i = t; i < BSZ/16; i += 256) dst[i] = src[i];
    }

    const int mw = wid & 3, nw = wid >> 2;
    const int rid = lane & 7, grp = lane >> 3;
    const int qrow = lane >> 2, qc = lane & 3;
    const int arow = mw*32 + (grp & 1)*8 + rid;
    const int au0  = grp >> 1;
    const int bu0  = grp & 1;

    const int img = blockIdx.x / NS;
    const int sub = blockIdx.x % NS;
    constexpr int BASE = 128 / NS, REM = 128 % NS;
    const int r0y  = sub*BASE + (sub < REM ? sub : REM);
    const int len  = BASE + (sub < REM ? 1 : 0);
    const int yend = r0y + len;

    auto stage_row = [&](int yy) {
        const int slot = (yy + 1) & 3;
        const bool rowok = (yy >= 0) && (yy < HH);
        const int yyc = rowok ? yy : 0;
        const size_t rowbase = (size_t)((img << 7) + yyc) * 128 * CCH;
        for (int s = t; s < ROWPX*SEGJ; s += 256) {
            const int pxi = s / SEGJ, j = s - pxi*SEGJ;
            const int ix = pxi - 1;
            const bool ok = rowok && (ix >= 0) && (ix < WW);
            const int ixc = ok ? ix : 0;
            const void* g = (const void*)(Ah_g + rowbase + (size_t)ixc*CCH + j*8);
            const uint32_t d = sb + ABUF + (uint32_t)(slot*ROWSZ + pxi*STRIDE + j*16);
            cpasync16(d, g, ok);
        }
        CP_COMMIT();
    };

    auto baddr = [&](int btap, int nf, int kc) -> uint32_t {
        const int oc = nw*32 + nf*8 + rid;
        const int u  = kc*2 + bu0;
        return sb + BOFF + (uint32_t)(btap*BTAPSZ + oc*80 + u*16);
    };

    auto compute_tap = [&](uint32_t Abase, int btap, float (*ac)[4][4]) {
#pragma unroll
        for (int kc = 0; kc < 2; kc++) {
            uint32_t a0[4], a1[4];
            const uint32_t aoff = (uint32_t)((au0 + kc*2)*16);
            LDSM4(a0, Abase + (uint32_t)(arow       *STRIDE) + aoff);
            LDSM4(a1, Abase + (uint32_t)((arow + 16)*STRIDE) + aoff);
#pragma unroll
            for (int nf = 0; nf < 4; nf++) {
                uint32_t b0, b1;
                LDSM2(b0, b1, baddr(btap, nf, kc));
                MMA(ac[0][nf], a0, b0, b1);
                MMA(ac[1][nf], a1, b0, b1);
            }
        }
    };

    auto epilogue = [&](float (*ac)[4][4], const float* bsm,
                        ushortt* outT, float* aw, int y) {
        __syncthreads();                         // redsm reuse guard
        const size_t tile = (size_t)(img*128 + y);
        ushortt* ob = outT + tile*8192;
#pragma unroll
        for (int nf = 0; nf < 4; nf++) {
            const int c0 = nw*32 + nf*8 + qc*2;
            const float bb0 = bsm[c0], bb1 = bsm[c0 + 1];
            float s0 = 0.f, s1v = 0.f, q0 = 0.f, q1 = 0.f;
#pragma unroll
            for (int mi = 0; mi < 2; mi++)
#pragma unroll
                for (int rr = 0; rr < 2; rr++) {
                    const int row = mw*32 + mi*16 + rr*8 + qrow;
                    const float v0 = ac[mi][nf][rr*2 + 0] + bb0;
                    const float v1 = ac[mi][nf][rr*2 + 1] + bb1;
                    *(__half2*)(ob + (size_t)row*64 + c0) = __floats2half2_rn(v0, v1);
                    s0 += v0; s1v += v1;
                    q0 = fmaf(v0, v0, q0); q1 = fmaf(v1, v1, q1);
                }
#pragma unroll
            for (int off = 4; off < 32; off <<= 1) {
                s0  += __shfl_xor_sync(0xffffffffu, s0,  off);
                s1v += __shfl_xor_sync(0xffffffffu, s1v, off);
                q0  += __shfl_xor_sync(0xffffffffu, q0,  off);
                q1  += __shfl_xor_sync(0xffffffffu, q1,  off);
            }
            if (qrow == 0) {
                const int lc = nf*8 + qc*2;
                redsm[(wid*32 + lc)*2 + 0] = s0;
                redsm[(wid*32 + lc)*2 + 1] = q0;
                redsm[(wid*32 + lc + 1)*2 + 0] = s1v;
                redsm[(wid*32 + lc + 1)*2 + 1] = q1;
            }
        }
        __syncthreads();
        if (t < 64) {
            float s = 0.f, q = 0.f;
#pragma unroll
            for (int mwi = 0; mwi < 4; mwi++) {
                const int idx = (((t >> 5)*4 + mwi)*32 + (t & 31))*2;
                s += redsm[idx]; q += redsm[idx + 1];
            }
            aw[t*2 + 0] += s;
            aw[t*2 + 1] += q;
        }
    };

    stage_row(r0y - 1);
    stage_row(r0y);
    stage_row(r0y + 1);

    for (int oy = r0y; oy < yend; oy++) {
        __syncthreads();
        const bool st = (oy + 2 <= yend);
        if (st) { stage_row(oy + 2); CP_WAIT1(); }
        else    { CP_WAIT0(); }
        __syncthreads();

        float acc[2][4][4];
#pragma unroll
        for (int mi = 0; mi < 2; mi++)
#pragma unroll
            for (int nf = 0; nf < 4; nf++)
#pragma unroll
                for (int k = 0; k < 4; k++) acc[mi][nf][k] = 0.f;

#pragma unroll
        for (int ky = 0; ky < 3; ky++) {
            const uint32_t slotbase = sb + ABUF + (uint32_t)(((oy + ky) & 3) * ROWSZ);
#pragma unroll
            for (int kx = 0; kx < 3; kx++)
                compute_tap(slotbase + (uint32_t)(kx*STRIDE), ky*3 + kx, acc);
        }
        epilogue(acc, biasm, out0, accs, oy);

        {
            float accp[2][4][4];
#pragma unroll
            for (int mi = 0; mi < 2; mi++)
#pragma unroll
                for (int nf = 0; nf < 4; nf++)
#pragma unroll
                    for (int k = 0; k < 4; k++) accp[mi][nf][k] = 0.f;
            const uint32_t cbase = sb + ABUF + (uint32_t)(((oy + 1) & 3) * ROWSZ);
            compute_tap(cbase + (uint32_t)STRIDE, 9, accp);
            epilogue(accp, biasm + 64, out1, accs + 128, oy);
        }
    }

    __syncthreads();
    if (t < 128) {
        const int which = t >> 6, c = t & 63;
        float* pb = which ? part1 : part0;
        pb[(size_t)blockIdx.x*128 + c*2 + 0] = accs[which*128 + c*2 + 0];
        pb[(size_t)blockIdx.x*128 + c*2 + 1] = accs[which*128 + c*2 + 1];
    }
}

// ===========================================================================
// conv2: 2-row M=256 tiles, 6-slot ring, fused bnrp in staging. fp16 output.
// Per-CTA BN partial accumulation.
// ===========================================================================
__global__ void __launch_bounds__(256, 1)
conv2_k(const ushortt* __restrict__ S1g, const ushortt* __restrict__ Bimg,
        const float* __restrict__ bias0, const float* __restrict__ st1,
        ushortt* __restrict__ out0, float* __restrict__ part0)
{
    constexpr int CCH    = 64;
    constexpr int STRIDE = 144;
    constexpr int SEGJ   = 8;
    constexpr int ROWPX  = 130;
    constexpr int ROWSZ  = ROWPX * STRIDE;   // 18720
    constexpr int ABUF   = 3840;             // biasm/abn/bbn + redsm + accs[2][128]
    constexpr int BOFF   = ABUF + 6 * ROWSZ; // 116160
    constexpr int BTAPSZ = 64 * 128;
    constexpr int BSZ    = 9 * BTAPSZ;       // 73728

    extern __shared__ __align__(16) char smem[];
    const uint32_t sb = smem_u32(smem);
    const int t = threadIdx.x, wid = t >> 5, lane = t & 31;

    float* biasm = (float*)smem;                 // [64]
    float* abn   = (float*)(smem + 256);         // [64]
    float* bbn   = (float*)(smem + 512);         // [64]
    float* redsm = (float*)(smem + 768);         // [8][32][2]
    float* accs  = (float*)(smem + 2816);        // [2][128]

    if (t < 64) {
        biasm[t] = (t < CSP) ? bias0[t] : 0.f;
        abn[t]   = (t < CSP) ? st1[2*t]   : 0.f;
        bbn[t]   = (t < CSP) ? st1[2*t+1] : 0.f;
    }
    if (t < 256) accs[t] = 0.f;

    {
        const uint4* src = (const uint4*)Bimg;
        uint4* dst = (uint4*)(smem + BOFF);
        for (int i = t; i < BSZ/16; i += 256) dst[i] = src[i];
    }
    __syncthreads();   // abn/bbn + accs visible before convert

    const int mw = wid & 3, nw = wid >> 2;
    const int rid = lane & 7, grp = lane >> 3;
    const int qrow = lane >> 2, qc = lane & 3;
    const int rowr = mw >> 1;
    const int px0  = (mw & 1) * 64;
    const int arowb = px0 + (grp & 1)*8 + rid;
    const int au0  = grp >> 1;
    const int bu0  = grp & 1;

    const int img = blockIdx.x / 9;
    const int sub = blockIdx.x % 9;
    const int r0y  = (sub == 0) ? 0 : 16 + (sub - 1)*14;
    const int len  = (sub == 0) ? 16 : 14;
    const int yend = r0y + len;

    auto slotof = [&](int row) -> int { return (row + 1) % 6; };

    auto stage_row = [&](int yy) {
        const int slot = slotof(yy);
        const bool rowok = (yy >= 0) && (yy < HH);
        const int yyc = rowok ? yy : 0;
        const size_t rowbase = (size_t)((img << 7) + yyc) * 128 * CCH;
        for (int s = t; s < ROWPX*SEGJ; s += 256) {
            const int pxi = s / SEGJ, j = s - pxi*SEGJ;
            const int ix = pxi - 1;
            const bool ok = rowok && (ix >= 0) && (ix < WW);
            const int ixc = ok ? ix : 0;
            const void* g = (const void*)(S1g + rowbase + (size_t)ixc*CCH + j*8);
            const uint32_t d = sb + ABUF + (uint32_t)(slot*ROWSZ + pxi*STRIDE + j*16);
            cpasync16(d, g, ok);
        }
        CP_COMMIT();
    };

    auto convert_row = [&](int yy) {
        const bool rowok = (yy >= 0) && (yy < HH);
        char* slotp = smem + ABUF + slotof(yy)*ROWSZ;
        for (int p = t; p < ROWPX; p += 256) {
            char* pxp = slotp + p*STRIDE;
            if (!rowok || p == 0 || p == ROWPX-1) {
                const uint4 z = make_uint4(0u,0u,0u,0u);
#pragma unroll
                for (int j = 0; j < 8; j++) *(uint4*)(pxp + j*16) = z;
            } else {
                uint4 raw[8];
#pragma unroll
                for (int j = 0; j < 8; j++) raw[j] = *(const uint4*)(pxp + j*16);
                const __half2* rh = (const __half2*)raw;
                ushortt h[64];
                float q = 0.f;
#pragma unroll
                for (int c2 = 0; c2 < 32; c2++) {
                    float2 f = __half22float2(rh[c2]);
                    const int c0 = 2*c2, c1 = c0 + 1;
                    float r0 = fmaxf(fmaf(abn[c0], f.x, bbn[c0]), 0.f);
                    q = fmaf(r0, r0, q);
                    __half h0 = __float2half_rn(r0);
                    h[c0+1] = *(ushortt*)&h0;
                    if (c1 < CSP) {
                        float r1 = fmaxf(fmaf(abn[c1], f.y, bbn[c1]), 0.f);
                        q = fmaf(r1, r1, q);
                        __half h1 = __float2half_rn(r1);
                        h[c1+1] = *(ushortt*)&h1;
                    }
                }
                float tv = sqrtf(1.f + q);
                __half ht = __float2half_rn(tv);
                h[0] = *(ushortt*)&ht;
#pragma unroll
                for (int j = 0; j < 8; j++) *(uint4*)(pxp + j*16) = ((uint4*)h)[j];
            }
        }
    };

    auto baddr = [&](int btap, int nf, int kc) -> uint32_t {
        const int oc = nw*32 + nf*8 + rid;
        const int u  = kc*2 + bu0;
        return sb + BOFF + (uint32_t)(btap*BTAPSZ + oc*128 + ((u ^ (oc & 7)) * 16));
    };

    stage_row(r0y - 1);
    stage_row(r0y);
    stage_row(r0y + 1);
    stage_row(r0y + 2);
    CP_WAIT2();
    __syncthreads();
    convert_row(r0y - 1);
    convert_row(r0y);

    for (int oy = r0y; oy < yend; oy += 2) {
        __syncthreads();                        // ring-slot + redsm reuse guard
        const bool st = (oy + 2 < yend);
        if (st) { stage_row(oy + 3); stage_row(oy + 4); CP_WAIT2(); }
        else    { CP_WAIT0(); }
        __syncthreads();
        convert_row(oy + 1);
        convert_row(oy + 2);
        __syncthreads();

        float acc[4][4][4];
#pragma unroll
        for (int i = 0; i < 4; i++)
#pragma unroll
            for (int nf = 0; nf < 4; nf++)
#pragma unroll
                for (int k = 0; k < 4; k++) acc[i][nf][k] = 0.f;

#pragma unroll
        for (int ky = 0; ky < 3; ky++) {
            const int inrow = oy + rowr + ky - 1;
            const uint32_t slotb = sb + ABUF + (uint32_t)(slotof(inrow) * ROWSZ);
#pragma unroll
            for (int kx = 0; kx < 3; kx++) {
                const int tap = ky*3 + kx;
                const uint32_t Abase = slotb + (uint32_t)(kx*STRIDE);
#pragma unroll
                for (int kc = 0; kc < 4; kc++) {
                    uint32_t a[4][4];
                    const uint32_t aoff = (uint32_t)((au0 + kc*2)*16);
#pragma unroll
                    for (int i = 0; i < 4; i++)
                        LDSM4(a[i], Abase + (uint32_t)((arowb + i*16)*STRIDE) + aoff);
#pragma unroll
                    for (int nf = 0; nf < 4; nf++) {
                        uint32_t b0, b1;
                        LDSM2(b0, b1, baddr(tap, nf, kc));
                        MMA(acc[0][nf], a[0], b0, b1);
                        MMA(acc[1][nf], a[1], b0, b1);
                        MMA(acc[2][nf], a[2], b0, b1);
                        MMA(acc[3][nf], a[3], b0, b1);
                    }
                }
            }
        }

        {
            const size_t tile = (size_t)(img*128 + oy + rowr);
            ushortt* ob = out0 + tile*8192;
#pragma unroll
            for (int nf = 0; nf < 4; nf++) {
                const int c0 = nw*32 + nf*8 + qc*2;
                const float bb0 = biasm[c0], bb1 = biasm[c0 + 1];
                float s0 = 0.f, s1v = 0.f, q0 = 0.f, q1 = 0.f;
#pragma unroll
                for (int i = 0; i < 4; i++)
#pragma unroll
                    for (int rr = 0; rr < 2; rr++) {
                        const int px = px0 + i*16 + rr*8 + qrow;
                        const float v0 = acc[i][nf][rr*2 + 0] + bb0;
                        const float v1 = acc[i][nf][rr*2 + 1] + bb1;
                        *(__half2*)(ob + (size_t)px*64 + c0) = __floats2half2_rn(v0, v1);
                        s0 += v0; s1v += v1;
                        q0 = fmaf(v0, v0, q0); q1 = fmaf(v1, v1, q1);
                    }
#pragma unroll
                for (int off = 4; off < 32; off <<= 1) {
                    s0  += __shfl_xor_sync(0xffffffffu, s0,  off);
                    s1v += __shfl_xor_sync(0xffffffffu, s1v, off);
                    q0  += __shfl_xor_sync(0xffffffffu, q0,  off);
                    q1  += __shfl_xor_sync(0xffffffffu, q1,  off);
                }
                if (qrow == 0) {
                    const int lc = nf*8 + qc*2;
                    redsm[(wid*32 + lc)*2 + 0] = s0;
                    redsm[(wid*32 + lc)*2 + 1] = q0;
                    redsm[(wid*32 + lc + 1)*2 + 0] = s1v;
                    redsm[(wid*32 + lc + 1)*2 + 1] = q1;
                }
            }
            __syncthreads();
            if (t < 128) {
                const int r = t >> 6, c = t & 63;
                const int w0 = (c >> 5)*4 + 2*r;
                const int i0 = (w0*32 + (c & 31))*2;
                const float s = redsm[i0] + redsm[i0 + 64];
                const float q = redsm[i0 + 1] + redsm[i0 + 65];
                accs[r*128 + c*2 + 0] += s;
                accs[r*128 + c*2 + 1] += q;
            }
        }
    }

    __syncthreads();
    if (t < 64) {
        part0[(size_t)blockIdx.x*128 + t*2 + 0] = accs[t*2 + 0] + accs[128 + t*2 + 0];
        part0[(size_t)blockIdx.x*128 + t*2 + 1] = accs[t*2 + 1] + accs[128 + t*2 + 1];
    }
}

// ---------------------------------------------------------------------------
// x NCHW fp32 -> NHWC fp16
__global__ __launch_bounds__(256)
void splitx_k(const float* __restrict__ x, ushortt* __restrict__ xh)
{
    int px = blockIdx.x*256 + threadIdx.x;
    int b = px >> 14, pix = px & (HWSZ - 1);
    const float* xb = x + (size_t)b*32*HWSZ + pix;
    ushortt h[32];
#pragma unroll
    for (int c = 0; c < 32; c++) {
        __half hh = __float2half_rn(xb[(size_t)c*HWSZ]);
        h[c] = *(ushortt*)&hh;
    }
    uint4* dh = (uint4*)(xh + (size_t)px*32);
#pragma unroll
    for (int i = 0; i < 4; i++) dh[i] = ((uint4*)h)[i];
}

// w1 + wp -> fp16 B1 image (padded 80B rows)
__global__ __launch_bounds__(256)
void splitw1_k(const float* __restrict__ w1, const float* __restrict__ wp,
               ushortt* __restrict__ B1)
{
    const int i = blockIdx.x*256 + threadIdx.x;
    if (i >= 25600) return;
    int tap = i / 2560, r2 = i % 2560, oc = r2 / 40, s = r2 % 40;
    float val = 0.f;
    if (s < 32 && oc < CSP) {
        if (tap < 9) { int ky = tap/3, kx = tap%3; val = w1[((oc*32 + s)*3 + ky)*3 + kx]; }
        else         { val = wp[oc*32 + s]; }
    }
    __half hv = __float2half_rn(val);
    B1[i] = *(ushortt*)&hv;
}

// w2 -> fp16 B2 image (SW128-xor 128B rows)
__global__ __launch_bounds__(256)
void splitw2_k(const float* __restrict__ w2, ushortt* __restrict__ B2)
{
    const int k = blockIdx.x*256 + threadIdx.x;
    if (k >= 36864) return;
    int tap = k / 4096, r2 = k % 4096, oc = r2 / 64, ps = r2 % 64;
    int u_log = (ps >> 3) ^ (oc & 7);
    int c = u_log*8 + (ps & 7);
    float val = 0.f;
    if (oc < CSP) { int ky = tap/3, kx = tap%3; val = w2[((oc*64 + c)*3 + ky)*3 + kx]; }
    __half hv = __float2half_rn(val);
    B2[k] = *(ushortt*)&hv;
}

// BN finalize over per-CTA partials (nA/nB CTAs). Two stats per grid.
__global__ __launch_bounds__(512)
void statsc_k(const float* __restrict__ partA, int nA,
              const float* __restrict__ gA, const float* __restrict__ btA,
              float* __restrict__ stA,
              const float* __restrict__ partB, int nB,
              const float* __restrict__ gB, const float* __restrict__ btB,
              float* __restrict__ stB)
{
    __shared__ double ss[512], qq[512];
    const bool second = (blockIdx.x >= 63);
    const int c = second ? (blockIdx.x - 63) : blockIdx.x;
    const float* part = second ? partB : partA;
    const int n = second ? nB : nA;
    const float* gamma = second ? gB : gA;
    const float* beta  = second ? btB : btA;
    float* stats = second ? stB : stA;
    const int t = threadIdx.x;
    double s = 0.0, q = 0.0;
    for (int i = t; i < n; i += 512) {
        s += (double)part[(size_t)i*128 + c*2 + 0];
        q += (double)part[(size_t)i*128 + c*2 + 1];
    }
    ss[t] = s; qq[t] = q;
#pragma unroll
    for (int off = 256; off > 0; off >>= 1) {
        __syncthreads();
        if (t < off) { ss[t] += ss[t+off]; qq[t] += qq[t+off]; }
    }
    if (t == 0) {
        const double nn = (double)NPX;
        double mu  = ss[0] / nn;
        double var = qq[0] / nn - mu*mu;
        float rstd = (float)(1.0 / sqrt(var + 1e-5));
        float a  = gamma[c] * rstd;
        float bc = beta[c] - a * (float)mu;
        stats[c*2] = a; stats[c*2+1] = bc;
    }
}

// merge + relu + project -> out NCHW fp32; s2/sp fp16
__global__ __launch_bounds__(256)
void final_k(const ushortt* __restrict__ s2, const ushortt* __restrict__ sp,
             const float* __restrict__ st2, const float* __restrict__ stp,
             float* __restrict__ out)
{
    __shared__ float a2[64], b2[64], ap[64], bp[64];
    int t = threadIdx.x;
    if (t < 64) {
        a2[t] = (t < CSP) ? st2[2*t]   : 0.f;
        b2[t] = (t < CSP) ? st2[2*t+1] : 0.f;
        ap[t] = (t < CSP) ? stp[2*t]   : 0.f;
        bp[t] = (t < CSP) ? stp[2*t+1] : 0.f;
    }
    __syncthreads();
    size_t px = (size_t)blockIdx.x*256 + t;
    int b = (int)(px >> 14), pix = (int)(px & (HWSZ - 1));
    const __half2* p2 = (const __half2*)(s2 + px*64);
    const __half2* pq = (const __half2*)(sp + px*64);
    float r[CSP]; float q = 0.f;
#pragma unroll
    for (int c2 = 0; c2 < 32; c2++) {
        float2 f2 = __half22float2(p2[c2]);
        float2 fq = __half22float2(pq[c2]);
        const int c0 = 2*c2, c1 = 2*c2 + 1;
        float h0 = fmaf(a2[c0], f2.x, b2[c0]) + fmaf(ap[c0], fq.x, bp[c0]);
        r[c0] = fmaxf(h0, 0.f);
        q = fmaf(r[c0], r[c0], q);
        if (c1 < CSP) {
            float h1 = fmaf(a2[c1], f2.y, b2[c1]) + fmaf(ap[c1], fq.y, bp[c1]);
            r[c1] = fmaxf(h1, 0.f);
            q = fmaf(r[c1], r[c1], q);
        }
    }
    float* ob = out + (size_t)b*64*HWSZ + pix;
    ob[0] = sqrtf(1.f + q);
#pragma unroll
    for (int c = 0; c < CSP; c++) ob[(size_t)(c+1)*HWSZ] = r[c];
}

// ---------------------------------------------------------------------------
extern "C" void kernel_launch(void* const* d_in, const int* in_sizes, int n_in,
                              void* d_out, int out_size)
{
    const float* x   = (const float*)d_in[0];
    const float* w1  = (const float*)d_in[1];
    const float* b1  = (const float*)d_in[2];
    const float* g1  = (const float*)d_in[3];
    const float* bt1 = (const float*)d_in[4];
    const float* w2  = (const float*)d_in[5];
    const float* b2  = (const float*)d_in[6];
    const float* g2  = (const float*)d_in[7];
    const float* bt2 = (const float*)d_in[8];
    const float* wp  = (const float*)d_in[9];
    const float* bp  = (const float*)d_in[10];
    const float* gp  = (const float*)d_in[11];
    const float* btp = (const float*)d_in[12];
    float* out = (float*)d_out;

    void *pxh,*ps1,*ps2,*psp,*pB1,*pB2,*ppart,*pstats;
    cudaGetSymbolAddress(&pxh, g_xh);
    cudaGetSymbolAddress(&ps1, g_s1);
    cudaGetSymbolAddress(&ps2, g_s2);
    cudaGetSymbolAddress(&psp, g_spb);  cudaGetSymbolAddress(&pB1, g_B1);
    cudaGetSymbolAddress(&pB2, g_B2);   cudaGetSymbolAddress(&ppart, g_part);
    cudaGetSymbolAddress(&pstats, g_stats);
    ushortt* xh = (ushortt*)pxh;
    ushortt* s1 = (ushortt*)ps1;
    ushortt* s2 = (ushortt*)ps2;
    ushortt* sp = (ushortt*)psp;
    ushortt* B1 = (ushortt*)pB1;
    ushortt* B2 = (ushortt*)pB2;
    float* part  = (float*)ppart;
    float* stats = (float*)pstats;

    const int SM1 = 3584 + 4*(130*80)  + 10*64*80;   // 96,384  (2 CTAs/SM)
    const int SM2 = 3840 + 6*(130*144) + 9*64*128;   // 189,888 (1 CTA/SM)
    cudaFuncSetAttribute((const void*)conv1_k,
                         cudaFuncAttributeMaxDynamicSharedMemorySize, SM1);
    cudaFuncSetAttribute((const void*)conv2_k,
                         cudaFuncAttributeMaxDynamicSharedMemorySize, SM2);

    splitw1_k<<<100, 256>>>(w1, wp, B1);
    splitw2_k<<<144, 256>>>(w2, B2);
    splitx_k<<<NPX/256, 256>>>(x, xh);
    // conv1 (288 CTAs) -> s1, sp + per-CTA partials
    conv1_k<<<16*18, 256, SM1>>>(xh, B1, b1, bp, s1, sp,
                                 part + 0*(size_t)PSZ, part + 1*(size_t)PSZ);
    statsc_k<<<63, 512>>>(part + 0*(size_t)PSZ, 288, g1, bt1, stats + 0*64*2,
                          nullptr, 0, nullptr, nullptr, nullptr);
    // conv2 (144 CTAs, fused bnrp) -> s2 + per-CTA partials
    conv2_k<<<16*9, 256, SM2>>>(s1, B2, b2, stats + 0*64*2, s2,
                                part + 2*(size_t)PSZ);
    statsc_k<<<126, 512>>>(part + 2*(size_t)PSZ, 144, g2, bt2, stats + 1*64*2,
                           part + 1*(size_t)PSZ, 288, gp, btp, stats + 2*64*2);
    final_k<<<NPX/256, 256>>>(s2, sp, stats + 1*64*2, stats + 2*64*2, out);
}